// round 5
// baseline (speedup 1.0000x reference)
#include <cuda_runtime.h>
#include <cuda_bf16.h>
#include <cstdint>

#define B_    16
#define S_    16
#define D_    4096
#define H_    32
#define KVH_  8
#define HD_   128
#define NREP_ 4
#define MAXS_ 4096
#define MROWS 256
#define KS    4        // K-split factor for projection GEMMs
#define NC    6144     // qkv unified output columns (4096 q + 1024 k + 1024 v)
#define SPLITS 8       // attention KV splits
#define TPS   512      // tokens per split

__device__ float  g_q  [MROWS * D_];
__device__ float  g_kn [MROWS * KVH_ * HD_];
__device__ float  g_vn [MROWS * KVH_ * HD_];
__device__ float  g_ctx[MROWS * D_];
__device__ float  g_p  [KS][MROWS * NC];   // GEMM partials
__device__ float2 g_tab[S_ * 64];          // rope cos/sin [s][pp]
__device__ float  g_ao [SPLITS * 128 * 64 * 128];  // attention partial O
__device__ float  g_am [SPLITS * 128 * 64];        // partial row max
__device__ float  g_al [SPLITS * 128 * 64];        // partial row sum

__device__ __forceinline__ unsigned f2tf(float x) {
    unsigned r; asm("cvt.rna.tf32.f32 %0, %1;" : "=r"(r) : "f"(x)); return r;
}
__device__ __forceinline__ void mma8(float* d, unsigned a0, unsigned a1, unsigned a2,
                                     unsigned a3, unsigned b0, unsigned b1) {
    asm volatile(
        "mma.sync.aligned.m16n8k8.row.col.f32.tf32.tf32.f32 "
        "{%0,%1,%2,%3}, {%4,%5,%6,%7}, {%8,%9}, {%0,%1,%2,%3};"
        : "+f"(d[0]), "+f"(d[1]), "+f"(d[2]), "+f"(d[3])
        : "r"(a0), "r"(a1), "r"(a2), "r"(a3), "r"(b0), "r"(b1));
}
__device__ __forceinline__ void cpa16(float* s, const float* g) {
    unsigned sa = (unsigned)__cvta_generic_to_shared(s);
    asm volatile("cp.async.cg.shared.global [%0], [%1], 16;" :: "r"(sa), "l"(g));
}
__device__ __forceinline__ void cp_commit() { asm volatile("cp.async.commit_group;"); }
template<int N> __device__ __forceinline__ void cp_wait() {
    asm volatile("cp.async.wait_group %0;" :: "n"(N));
}
#define PAIR_BAR(id) asm volatile("bar.sync %0, 64;" :: "r"(id) : "memory")

// ======================= rope table =======================
__global__ void rope_tab_kernel(const int* __restrict__ sp) {
    int idx = threadIdx.x;            // 1024 threads: s(4b) x pp(6b)
    int s = idx >> 6, pp = idx & 63;
    double f = (double)(sp[0] + s) * exp(-9.210340371976184 * ((double)pp / 64.0));
    double cd, sd; sincos(f, &sd, &cd);
    g_tab[idx] = make_float2((float)cd, (float)sd);
}

// ======================= GEMM 128x128, K-split =======================
#define BM 128
#define BK 32
#define AST 36
#define BST 136
#define GEMM_SMEM_BYTES ((2*BM*AST + 2*BK*BST) * 4)

__device__ void gemm_tile(const float* __restrict__ A, int lda,
                          const float* __restrict__ W, int ldw,
                          float* __restrict__ C, int ldc,
                          int m0, int n0w, int n0c, int kbase, int KT)
{
    extern __shared__ float sm[];
    float* As0 = sm;
    float* As1 = sm + BM * AST;
    float* Bs0 = sm + 2 * BM * AST;
    float* Bs1 = sm + 2 * BM * AST + BK * BST;

    int tid = threadIdx.x, lane = tid & 31, wid = tid >> 5;
    int wm = wid >> 2, wn = wid & 3;
    int gr = lane >> 2, kq = lane & 3;

    float acc[4][4][4];
#pragma unroll
    for (int mt = 0; mt < 4; mt++)
#pragma unroll
        for (int nt = 0; nt < 4; nt++)
#pragma unroll
            for (int i = 0; i < 4; i++) acc[mt][nt][i] = 0.f;

    {
#pragma unroll
        for (int i = 0; i < 4; i++) {
            int idx = i * 256 + tid; int r = idx >> 3, c4 = idx & 7;
            cpa16(As0 + r * AST + c4 * 4, A + (long)(m0 + r) * lda + kbase + c4 * 4);
        }
#pragma unroll
        for (int i = 0; i < 4; i++) {
            int idx = i * 256 + tid; int r = idx >> 5, c4 = idx & 31;
            cpa16(Bs0 + r * BST + c4 * 4, W + (long)(kbase + r) * ldw + n0w + c4 * 4);
        }
        cp_commit();
    }

    for (int kt = 0; kt < KT; kt++) {
        float* Ab = (kt & 1) ? As1 : As0;
        float* Bb = (kt & 1) ? Bs1 : Bs0;
        if (kt + 1 < KT) {
            float* An = (kt & 1) ? As0 : As1;
            float* Bn = (kt & 1) ? Bs0 : Bs1;
            int k1 = kbase + (kt + 1) * BK;
#pragma unroll
            for (int i = 0; i < 4; i++) {
                int idx = i * 256 + tid; int r = idx >> 3, c4 = idx & 7;
                cpa16(An + r * AST + c4 * 4, A + (long)(m0 + r) * lda + k1 + c4 * 4);
            }
#pragma unroll
            for (int i = 0; i < 4; i++) {
                int idx = i * 256 + tid; int r = idx >> 5, c4 = idx & 31;
                cpa16(Bn + r * BST + c4 * 4, W + (long)(k1 + r) * ldw + n0w + c4 * 4);
            }
            cp_commit();
            cp_wait<1>();
        } else {
            cp_wait<0>();
        }
        __syncthreads();
#pragma unroll
        for (int kk = 0; kk < 4; kk++) {
            unsigned af[4][4], bf[4][2];
#pragma unroll
            for (int mt = 0; mt < 4; mt++) {
                int rm = wm * 64 + mt * 16;
                const float* p0 = Ab + (rm + gr) * AST + kk * 8 + kq;
                const float* p1 = Ab + (rm + gr + 8) * AST + kk * 8 + kq;
                af[mt][0] = f2tf(p0[0]); af[mt][1] = f2tf(p1[0]);
                af[mt][2] = f2tf(p0[4]); af[mt][3] = f2tf(p1[4]);
            }
#pragma unroll
            for (int nt = 0; nt < 4; nt++) {
                int cb = wn * 32 + nt * 8 + gr;
                bf[nt][0] = f2tf(Bb[(kk * 8 + kq) * BST + cb]);
                bf[nt][1] = f2tf(Bb[(kk * 8 + kq + 4) * BST + cb]);
            }
#pragma unroll
            for (int mt = 0; mt < 4; mt++)
#pragma unroll
                for (int nt = 0; nt < 4; nt++)
                    mma8(acc[mt][nt], af[mt][0], af[mt][1], af[mt][2], af[mt][3],
                         bf[nt][0], bf[nt][1]);
        }
        __syncthreads();
    }

#pragma unroll
    for (int mt = 0; mt < 4; mt++)
#pragma unroll
        for (int nt = 0; nt < 4; nt++) {
            int row = m0 + wm * 64 + mt * 16 + gr;
            int col = n0c + wn * 32 + nt * 8 + 2 * kq;
            *(float2*)(C + (long)row * ldc + col) =
                make_float2(acc[mt][nt][0], acc[mt][nt][1]);
            *(float2*)(C + (long)(row + 8) * ldc + col) =
                make_float2(acc[mt][nt][2], acc[mt][nt][3]);
        }
}

__global__ void qkv_kernel(const float* __restrict__ x, const float* __restrict__ Wq,
                           const float* __restrict__ Wk, const float* __restrict__ Wv) {
    int y = blockIdx.y, z = blockIdx.z;
    const float* W; int ldw, n0w, n0c;
    if (y < 32)      { W = Wq; ldw = 4096; n0w = y * 128;        n0c = y * 128; }
    else if (y < 40) { W = Wk; ldw = 1024; n0w = (y - 32) * 128; n0c = 4096 + (y - 32) * 128; }
    else             { W = Wv; ldw = 1024; n0w = (y - 40) * 128; n0c = 5120 + (y - 40) * 128; }
    gemm_tile(x, 4096, W, ldw, g_p[z], NC, blockIdx.x * BM, n0w, n0c, z * 1024, 32);
}

__global__ void out_kernel(const float* __restrict__ Wo) {
    int z = blockIdx.z;
    gemm_tile(g_ctx, 4096, Wo, 4096, g_p[z], 4096,
              blockIdx.x * BM, blockIdx.y * 128, blockIdx.y * 128, z * 1024, 32);
}

// ======================= combines =======================
__global__ void qkv_combine_kernel() {
    int idx = blockIdx.x * 256 + threadIdx.x;      // 786432 pairs
    int row = idx / (NC / 2);
    int p   = idx - row * (NC / 2);
    int col = 2 * p;
    float v0 = 0.f, v1 = 0.f;
#pragma unroll
    for (int h = 0; h < KS; h++) {
        const float* src = g_p[h] + (long)row * NC + col;
        v0 += src[0]; v1 += src[1];
    }
    if (col < 4096) {
        int pp = (col & 127) >> 1;
        float2 cs = g_tab[((row & 15) << 6) + pp];
        const float qs = 0.08838834764831845f;
        float t = (v0 * cs.x - v1 * cs.y) * qs;
        v1 = (v0 * cs.y + v1 * cs.x) * qs; v0 = t;
        *(float2*)(g_q + (long)row * 4096 + col) = make_float2(v0, v1);
    } else if (col < 5120) {
        int c2 = col - 4096;
        int pp = (c2 & 127) >> 1;
        float2 cs = g_tab[((row & 15) << 6) + pp];
        float t = v0 * cs.x - v1 * cs.y;
        v1 = v0 * cs.y + v1 * cs.x; v0 = t;
        *(float2*)(g_kn + (long)row * 1024 + c2) = make_float2(v0, v1);
    } else {
        *(float2*)(g_vn + (long)row * 1024 + (col - 5120)) = make_float2(v0, v1);
    }
}

__global__ void out_combine_kernel(float* __restrict__ out) {
    int idx = blockIdx.x * 256 + threadIdx.x;      // 262144 float4s
    float4 a = *(const float4*)(g_p[0] + 4 * (long)idx);
    float4 b = *(const float4*)(g_p[1] + 4 * (long)idx);
    float4 c = *(const float4*)(g_p[2] + 4 * (long)idx);
    float4 d = *(const float4*)(g_p[3] + 4 * (long)idx);
    *(float4*)(out + 4 * (long)idx) =
        make_float4(a.x + b.x + c.x + d.x, a.y + b.y + c.y + d.y,
                    a.z + b.z + c.z + d.z, a.w + b.w + c.w + d.w);
}

// ======================= attention (split-KV, 256 threads, TC=32) =======================
#define TC   32
#define KSTR 132
#define VSTR 136
#define PST  36
#define AOFF_K0  0
#define AOFF_K1  (TC*KSTR)
#define AOFF_V0  (2*TC*KSTR)
#define AOFF_V1  (AOFF_V0 + TC*VSTR)
#define AOFF_P   (AOFF_V1 + TC*VSTR)
#define AOFF_EX  (AOFF_P + 64*PST)
#define ATTN_SMEM_BYTES ((AOFF_EX + 256) * 4)

__device__ __forceinline__ void attn_load_kv(
    const float* __restrict__ cache_k, const float* __restrict__ cache_v,
    int b, int kvh, int start, int kvlen, int t0, float* Ks, float* Vs, int tid)
{
#pragma unroll
    for (int i = 0; i < 4; i++) {
        int idx = i * 256 + tid; int r = idx >> 5, c4 = idx & 31;
        int t = t0 + r;
        if (t < start) {
            long o = ((((long)b * MAXS_ + t) * KVH_) + kvh) * HD_ + c4 * 4;
            cpa16(Ks + r * KSTR + c4 * 4, cache_k + o);
            cpa16(Vs + r * VSTR + c4 * 4, cache_v + o);
        } else if (t < kvlen) {
            long o = (((long)(b * S_ + (t - start))) * KVH_ + kvh) * HD_ + c4 * 4;
            cpa16(Ks + r * KSTR + c4 * 4, g_kn + o);
            cpa16(Vs + r * VSTR + c4 * 4, g_vn + o);
        } else {
            *(float4*)(Ks + r * KSTR + c4 * 4) = make_float4(0.f, 0.f, 0.f, 0.f);
            *(float4*)(Vs + r * VSTR + c4 * 4) = make_float4(0.f, 0.f, 0.f, 0.f);
        }
    }
    cp_commit();
}

__global__ void __launch_bounds__(256, 2)
attn_kernel(const float* __restrict__ cache_k,
            const float* __restrict__ cache_v,
            const int* __restrict__ sp)
{
    extern __shared__ float sm[];
    float* Ksb[2] = { sm + AOFF_K0, sm + AOFF_K1 };
    float* Vsb[2] = { sm + AOFF_V0, sm + AOFF_V1 };
    float* Ps = sm + AOFF_P;
    float* ex = sm + AOFF_EX;  // [0:128) m partials, [128:256) l partials

    int tid = threadIdx.x, lane = tid & 31, wid = tid >> 5;
    int bkvh = blockIdx.x;
    int b = bkvh >> 3, kvh = bkvh & 7;
    int split = blockIdx.y;
    int start = sp[0], kvlen = start + S_;
    int wm = wid & 3, wn = wid >> 2;        // 4 m-groups x 2 n-groups; pair = wid^4
    int gr = lane >> 2, kq = lane & 3;
    int rm = wm * 16;

    int t0s = split * TPS;
    int t1s = min(t0s + TPS, kvlen);
    int NCH = (t1s > t0s) ? (t1s - t0s + TC - 1) / TC : 0;

    // ---- Q fragments resident in registers ----
    unsigned qa[16][4];
    {
        int r0 = rm + gr, r1 = r0 + 8;
        const float* q0 = g_q + (long)(b * S_ + (r0 & 15)) * D_ + (kvh * NREP_ + (r0 >> 4)) * HD_;
        const float* q1 = g_q + (long)(b * S_ + (r1 & 15)) * D_ + (kvh * NREP_ + (r1 >> 4)) * HD_;
#pragma unroll
        for (int kk = 0; kk < 16; kk++) {
            qa[kk][0] = f2tf(q0[kk * 8 + kq]);
            qa[kk][1] = f2tf(q1[kk * 8 + kq]);
            qa[kk][2] = f2tf(q0[kk * 8 + kq + 4]);
            qa[kk][3] = f2tf(q1[kk * 8 + kq + 4]);
        }
    }

    float m0r = -1e30f, m1r = -1e30f, l0r = 0.f, l1r = 0.f;
    float cacc[8][4];
#pragma unroll
    for (int nt = 0; nt < 8; nt++)
#pragma unroll
        for (int i = 0; i < 4; i++) cacc[nt][i] = 0.f;

    if (NCH > 0) {
        attn_load_kv(cache_k, cache_v, b, kvh, start, kvlen, t0s, Ksb[0], Vsb[0], tid);
        if (NCH > 1) {
            attn_load_kv(cache_k, cache_v, b, kvh, start, kvlen, t0s + TC, Ksb[1], Vsb[1], tid);
            cp_wait<1>();
        } else {
            cp_wait<0>();
        }
        __syncthreads();
    }

    for (int j = 0; j < NCH; j++) {
        const float* Kb = Ksb[j & 1];
        const float* Vb = Vsb[j & 1];

        // ---- S = Q K^T : warp covers cols [wn*16, wn*16+16) ----
        float sacc[2][4];
#pragma unroll
        for (int nt = 0; nt < 2; nt++)
#pragma unroll
            for (int i = 0; i < 4; i++) sacc[nt][i] = 0.f;
#pragma unroll
        for (int kk = 0; kk < 16; kk++) {
#pragma unroll
            for (int nt = 0; nt < 2; nt++) {
                int cb = wn * 16 + nt * 8 + gr;
                unsigned b0 = f2tf(Kb[cb * KSTR + kk * 8 + kq]);
                unsigned b1 = f2tf(Kb[cb * KSTR + kk * 8 + kq + 4]);
                mma8(sacc[nt], qa[kk][0], qa[kk][1], qa[kk][2], qa[kk][3], b0, b1);
            }
        }

        // tail mask within this split
        if (j == NCH - 1 && ((t1s - t0s) & (TC - 1))) {
#pragma unroll
            for (int nt = 0; nt < 2; nt++) {
                int cb = t0s + j * TC + wn * 16 + nt * 8 + 2 * kq;
                if (cb >= t1s)     { sacc[nt][0] = -1e30f; sacc[nt][2] = -1e30f; }
                if (cb + 1 >= t1s) { sacc[nt][1] = -1e30f; sacc[nt][3] = -1e30f; }
            }
        }

        // ---- online softmax (pair of wn warps) ----
        float mw0 = fmaxf(fmaxf(sacc[0][0], sacc[0][1]), fmaxf(sacc[1][0], sacc[1][1]));
        float mw1 = fmaxf(fmaxf(sacc[0][2], sacc[0][3]), fmaxf(sacc[1][2], sacc[1][3]));
        mw0 = fmaxf(mw0, __shfl_xor_sync(0xffffffffu, mw0, 1));
        mw0 = fmaxf(mw0, __shfl_xor_sync(0xffffffffu, mw0, 2));
        mw1 = fmaxf(mw1, __shfl_xor_sync(0xffffffffu, mw1, 1));
        mw1 = fmaxf(mw1, __shfl_xor_sync(0xffffffffu, mw1, 2));
        if (kq == 0) { ex[wn * 64 + rm + gr] = mw0; ex[wn * 64 + rm + gr + 8] = mw1; }
        PAIR_BAR(1 + wm);
        float M0 = fmaxf(fmaxf(mw0, ex[(1 - wn) * 64 + rm + gr]), m0r);
        float M1 = fmaxf(fmaxf(mw1, ex[(1 - wn) * 64 + rm + gr + 8]), m1r);

        float l0l = 0.f, l1l = 0.f;
#pragma unroll
        for (int nt = 0; nt < 2; nt++) {
            sacc[nt][0] = __expf(sacc[nt][0] - M0);
            sacc[nt][1] = __expf(sacc[nt][1] - M0);
            sacc[nt][2] = __expf(sacc[nt][2] - M1);
            sacc[nt][3] = __expf(sacc[nt][3] - M1);
            l0l += sacc[nt][0] + sacc[nt][1];
            l1l += sacc[nt][2] + sacc[nt][3];
        }
        l0l += __shfl_xor_sync(0xffffffffu, l0l, 1);
        l0l += __shfl_xor_sync(0xffffffffu, l0l, 2);
        l1l += __shfl_xor_sync(0xffffffffu, l1l, 1);
        l1l += __shfl_xor_sync(0xffffffffu, l1l, 2);
        if (kq == 0) { ex[128 + wn * 64 + rm + gr] = l0l; ex[128 + wn * 64 + rm + gr + 8] = l1l; }

        // store P (pre-converted to tf32 bits)
#pragma unroll
        for (int nt = 0; nt < 2; nt++) {
            int cb = wn * 16 + nt * 8 + 2 * kq;
            *(float2*)&Ps[(rm + gr) * PST + cb] =
                make_float2(__uint_as_float(f2tf(sacc[nt][0])),
                            __uint_as_float(f2tf(sacc[nt][1])));
            *(float2*)&Ps[(rm + gr + 8) * PST + cb] =
                make_float2(__uint_as_float(f2tf(sacc[nt][2])),
                            __uint_as_float(f2tf(sacc[nt][3])));
        }
        PAIR_BAR(1 + wm);

        float L0 = l0l + ex[128 + (1 - wn) * 64 + rm + gr];
        float L1 = l1l + ex[128 + (1 - wn) * 64 + rm + gr + 8];
        float sc0 = __expf(m0r - M0), sc1 = __expf(m1r - M1);
        l0r = l0r * sc0 + L0;  l1r = l1r * sc1 + L1;
        m0r = M0;  m1r = M1;
#pragma unroll
        for (int nt = 0; nt < 8; nt++) {
            cacc[nt][0] *= sc0; cacc[nt][1] *= sc0;
            cacc[nt][2] *= sc1; cacc[nt][3] *= sc1;
        }

        // ---- O += P V : warp covers dims [wn*64, wn*64+64) ----
#pragma unroll
        for (int kk = 0; kk < 4; kk++) {
            unsigned a0 = __float_as_uint(Ps[(rm + gr) * PST + kk * 8 + kq]);
            unsigned a1 = __float_as_uint(Ps[(rm + gr + 8) * PST + kk * 8 + kq]);
            unsigned a2 = __float_as_uint(Ps[(rm + gr) * PST + kk * 8 + kq + 4]);
            unsigned a3 = __float_as_uint(Ps[(rm + gr + 8) * PST + kk * 8 + kq + 4]);
#pragma unroll
            for (int nt = 0; nt < 8; nt++) {
                int dc = wn * 64 + nt * 8 + gr;
                unsigned b0 = f2tf(Vb[(kk * 8 + kq) * VSTR + dc]);
                unsigned b1 = f2tf(Vb[(kk * 8 + kq + 4) * VSTR + dc]);
                mma8(cacc[nt], a0, a1, a2, a3, b0, b1);
            }
        }

        cp_wait<0>();
        __syncthreads();
        if (j + 2 < NCH)
            attn_load_kv(cache_k, cache_v, b, kvh, start, kvlen,
                         t0s + (j + 2) * TC, Ksb[j & 1], Vsb[j & 1], tid);
    }

    // ---- epilogue: write UNNORMALIZED partials + (m, l) ----
    int r0 = rm + gr, r1 = r0 + 8;
    long ob = (long)(split * 128 + bkvh) * 64;
#pragma unroll
    for (int nt = 0; nt < 8; nt++) {
        int col = wn * 64 + nt * 8 + 2 * kq;
        *(float2*)(g_ao + (ob + r0) * 128 + col) = make_float2(cacc[nt][0], cacc[nt][1]);
        *(float2*)(g_ao + (ob + r1) * 128 + col) = make_float2(cacc[nt][2], cacc[nt][3]);
    }
    if (wn == 0 && kq == 0) {
        g_am[ob + r0] = m0r; g_am[ob + r1] = m1r;
        g_al[ob + r0] = l0r; g_al[ob + r1] = l1r;
    }
}

__global__ void attn_combine_kernel() {
    int idx = blockIdx.x * 256 + threadIdx.x;      // 128*64*32 = 262144
    int bkvh = idx >> 11;
    int rem = idx & 2047;
    int r = rem >> 5, d4 = rem & 31;
    int rowid = bkvh * 64 + r;

    float M = -1e30f;
#pragma unroll
    for (int s = 0; s < SPLITS; s++)
        M = fmaxf(M, g_am[s * 8192 + rowid]);

    float L = 0.f;
    float4 acc = make_float4(0.f, 0.f, 0.f, 0.f);
#pragma unroll
    for (int s = 0; s < SPLITS; s++) {
        float w = __expf(g_am[s * 8192 + rowid] - M);
        L += w * g_al[s * 8192 + rowid];
        float4 o = *(const float4*)(g_ao + ((long)s * 8192 + rowid) * 128 + d4 * 4);
        acc.x += w * o.x; acc.y += w * o.y; acc.z += w * o.z; acc.w += w * o.w;
    }
    float inv = 1.f / L;
    int b = bkvh >> 3, kvh = bkvh & 7;
    int st = r & 15, rep = r >> 4;
    long addr = ((long)(b * S_ + st)) * D_ + (kvh * NREP_ + rep) * HD_ + d4 * 4;
    *(float4*)(g_ctx + addr) =
        make_float4(acc.x * inv, acc.y * inv, acc.z * inv, acc.w * inv);
}

// ======================= launch =======================
extern "C" void kernel_launch(void* const* d_in, const int* in_sizes, int n_in,
                              void* d_out, int out_size) {
    const float* x       = (const float*)d_in[0];
    const float* Wq      = (const float*)d_in[1];
    const float* Wk      = (const float*)d_in[2];
    const float* Wv      = (const float*)d_in[3];
    const float* Wo      = (const float*)d_in[4];
    const float* cache_k = (const float*)d_in[5];
    const float* cache_v = (const float*)d_in[6];
    const int*   sp      = (const int*)d_in[7];
    float* out = (float*)d_out;

    cudaFuncSetAttribute(qkv_kernel,  cudaFuncAttributeMaxDynamicSharedMemorySize, GEMM_SMEM_BYTES);
    cudaFuncSetAttribute(out_kernel,  cudaFuncAttributeMaxDynamicSharedMemorySize, GEMM_SMEM_BYTES);
    cudaFuncSetAttribute(attn_kernel, cudaFuncAttributeMaxDynamicSharedMemorySize, ATTN_SMEM_BYTES);

    rope_tab_kernel<<<1, 1024>>>(sp);
    qkv_kernel<<<dim3(2, 48, KS), 256, GEMM_SMEM_BYTES>>>(x, Wq, Wk, Wv);
    qkv_combine_kernel<<<(MROWS * NC / 2) / 256, 256>>>();
    attn_kernel<<<dim3(128, SPLITS), 256, ATTN_SMEM_BYTES>>>(cache_k, cache_v, sp);
    attn_combine_kernel<<<(128 * 64 * 32) / 256, 256>>>();
    out_kernel<<<dim3(2, 32, KS), 256, GEMM_SMEM_BYTES>>>(Wo);
    out_combine_kernel<<<(MROWS * D_ / 4) / 256, 256>>>(out);
}

// round 7
// speedup vs baseline: 1.2560x; 1.2560x over previous
#include <cuda_runtime.h>
#include <cuda_bf16.h>
#include <cstdint>

#define B_    16
#define S_    16
#define D_    4096
#define H_    32
#define KVH_  8
#define HD_   128
#define NREP_ 4
#define MAXS_ 4096
#define MROWS 256
#define KS    4        // K-split factor for projection GEMMs
#define NC    6144     // qkv unified output columns

__device__ float  g_q  [MROWS * D_];
__device__ float  g_kn [MROWS * KVH_ * HD_];
__device__ float  g_vn [MROWS * KVH_ * HD_];
__device__ float  g_ctx[MROWS * D_];
__device__ float  g_p  [KS][MROWS * NC];   // GEMM partials
__device__ float2 g_tab[S_ * 64];          // rope cos/sin [s][pp]

__device__ __forceinline__ unsigned f2tf(float x) {
    unsigned r; asm("cvt.rna.tf32.f32 %0, %1;" : "=r"(r) : "f"(x)); return r;
}
__device__ __forceinline__ void mma8(float* d, unsigned a0, unsigned a1, unsigned a2,
                                     unsigned a3, unsigned b0, unsigned b1) {
    asm volatile(
        "mma.sync.aligned.m16n8k8.row.col.f32.tf32.tf32.f32 "
        "{%0,%1,%2,%3}, {%4,%5,%6,%7}, {%8,%9}, {%0,%1,%2,%3};"
        : "+f"(d[0]), "+f"(d[1]), "+f"(d[2]), "+f"(d[3])
        : "r"(a0), "r"(a1), "r"(a2), "r"(a3), "r"(b0), "r"(b1));
}
__device__ __forceinline__ void mma16h(float* d, unsigned a0, unsigned a1, unsigned a2,
                                       unsigned a3, unsigned b0, unsigned b1) {
    asm volatile(
        "mma.sync.aligned.m16n8k16.row.col.f32.f16.f16.f32 "
        "{%0,%1,%2,%3}, {%4,%5,%6,%7}, {%8,%9}, {%0,%1,%2,%3};"
        : "+f"(d[0]), "+f"(d[1]), "+f"(d[2]), "+f"(d[3])
        : "r"(a0), "r"(a1), "r"(a2), "r"(a3), "r"(b0), "r"(b1));
}
__device__ __forceinline__ float ex2f(float x) {
    float r; asm("ex2.approx.f32 %0, %1;" : "=f"(r) : "f"(x)); return r;
}
__device__ __forceinline__ unsigned packh2(float lo, float hi) {
    unsigned d; asm("cvt.rn.f16x2.f32 %0, %1, %2;" : "=r"(d) : "f"(hi), "f"(lo)); return d;
}
__device__ __forceinline__ unsigned h2ex2(unsigned x) {
    unsigned d; asm("ex2.approx.f16x2 %0, %1;" : "=r"(d) : "r"(x)); return d;
}
__device__ __forceinline__ unsigned hadd2u(unsigned a, unsigned b) {
    unsigned d; asm("add.f16x2 %0, %1, %2;" : "=r"(d) : "r"(a), "r"(b)); return d;
}
__device__ __forceinline__ float2 h2f2(unsigned h) {
    float2 f;
    asm("{.reg .f16 l, h; mov.b32 {l, h}, %2; cvt.f32.f16 %0, l; cvt.f32.f16 %1, h;}"
        : "=f"(f.x), "=f"(f.y) : "r"(h));
    return f;
}
__device__ __forceinline__ void cpa16(float* s, const float* g) {
    unsigned sa = (unsigned)__cvta_generic_to_shared(s);
    asm volatile("cp.async.cg.shared.global [%0], [%1], 16;" :: "r"(sa), "l"(g));
}
__device__ __forceinline__ void cp_commit() { asm volatile("cp.async.commit_group;"); }
template<int N> __device__ __forceinline__ void cp_wait() {
    asm volatile("cp.async.wait_group %0;" :: "n"(N));
}
#define GROUP_BAR(id) asm volatile("bar.sync %0, 128;" :: "r"(id) : "memory")

// ======================= rope table =======================
__global__ void rope_tab_kernel(const int* __restrict__ sp) {
    int idx = threadIdx.x;
    int s = idx >> 6, pp = idx & 63;
    double f = (double)(sp[0] + s) * exp(-9.210340371976184 * ((double)pp / 64.0));
    double cd, sd; sincos(f, &sd, &cd);
    g_tab[idx] = make_float2((float)cd, (float)sd);
}

// ======================= GEMM 128x128, K-split =======================
#define BM 128
#define BK 32
#define AST 36
#define BST 136
#define GEMM_SMEM_BYTES ((2*BM*AST + 2*BK*BST) * 4)

__device__ void gemm_tile(const float* __restrict__ A, int lda,
                          const float* __restrict__ W, int ldw,
                          float* __restrict__ C, int ldc,
                          int m0, int n0w, int n0c, int kbase, int KT)
{
    extern __shared__ float sm[];
    float* As0 = sm;
    float* As1 = sm + BM * AST;
    float* Bs0 = sm + 2 * BM * AST;
    float* Bs1 = sm + 2 * BM * AST + BK * BST;

    int tid = threadIdx.x, lane = tid & 31, wid = tid >> 5;
    int wm = wid >> 2, wn = wid & 3;
    int gr = lane >> 2, kq = lane & 3;

    float acc[4][4][4];
#pragma unroll
    for (int mt = 0; mt < 4; mt++)
#pragma unroll
        for (int nt = 0; nt < 4; nt++)
#pragma unroll
            for (int i = 0; i < 4; i++) acc[mt][nt][i] = 0.f;

    {
#pragma unroll
        for (int i = 0; i < 4; i++) {
            int idx = i * 256 + tid; int r = idx >> 3, c4 = idx & 7;
            cpa16(As0 + r * AST + c4 * 4, A + (long)(m0 + r) * lda + kbase + c4 * 4);
        }
#pragma unroll
        for (int i = 0; i < 4; i++) {
            int idx = i * 256 + tid; int r = idx >> 5, c4 = idx & 31;
            cpa16(Bs0 + r * BST + c4 * 4, W + (long)(kbase + r) * ldw + n0w + c4 * 4);
        }
        cp_commit();
    }

    for (int kt = 0; kt < KT; kt++) {
        float* Ab = (kt & 1) ? As1 : As0;
        float* Bb = (kt & 1) ? Bs1 : Bs0;
        if (kt + 1 < KT) {
            float* An = (kt & 1) ? As0 : As1;
            float* Bn = (kt & 1) ? Bs0 : Bs1;
            int k1 = kbase + (kt + 1) * BK;
#pragma unroll
            for (int i = 0; i < 4; i++) {
                int idx = i * 256 + tid; int r = idx >> 3, c4 = idx & 7;
                cpa16(An + r * AST + c4 * 4, A + (long)(m0 + r) * lda + k1 + c4 * 4);
            }
#pragma unroll
            for (int i = 0; i < 4; i++) {
                int idx = i * 256 + tid; int r = idx >> 5, c4 = idx & 31;
                cpa16(Bn + r * BST + c4 * 4, W + (long)(k1 + r) * ldw + n0w + c4 * 4);
            }
            cp_commit();
            cp_wait<1>();
        } else {
            cp_wait<0>();
        }
        __syncthreads();
#pragma unroll
        for (int kk = 0; kk < 4; kk++) {
            unsigned af[4][4], bf[4][2];
#pragma unroll
            for (int mt = 0; mt < 4; mt++) {
                int rm = wm * 64 + mt * 16;
                const float* p0 = Ab + (rm + gr) * AST + kk * 8 + kq;
                const float* p1 = Ab + (rm + gr + 8) * AST + kk * 8 + kq;
                af[mt][0] = f2tf(p0[0]); af[mt][1] = f2tf(p1[0]);
                af[mt][2] = f2tf(p0[4]); af[mt][3] = f2tf(p1[4]);
            }
#pragma unroll
            for (int nt = 0; nt < 4; nt++) {
                int cb = wn * 32 + nt * 8 + gr;
                bf[nt][0] = f2tf(Bb[(kk * 8 + kq) * BST + cb]);
                bf[nt][1] = f2tf(Bb[(kk * 8 + kq + 4) * BST + cb]);
            }
#pragma unroll
            for (int mt = 0; mt < 4; mt++)
#pragma unroll
                for (int nt = 0; nt < 4; nt++)
                    mma8(acc[mt][nt], af[mt][0], af[mt][1], af[mt][2], af[mt][3],
                         bf[nt][0], bf[nt][1]);
        }
        __syncthreads();
    }

#pragma unroll
    for (int mt = 0; mt < 4; mt++)
#pragma unroll
        for (int nt = 0; nt < 4; nt++) {
            int row = m0 + wm * 64 + mt * 16 + gr;
            int col = n0c + wn * 32 + nt * 8 + 2 * kq;
            *(float2*)(C + (long)row * ldc + col) =
                make_float2(acc[mt][nt][0], acc[mt][nt][1]);
            *(float2*)(C + (long)(row + 8) * ldc + col) =
                make_float2(acc[mt][nt][2], acc[mt][nt][3]);
        }
}

__global__ void qkv_kernel(const float* __restrict__ x, const float* __restrict__ Wq,
                           const float* __restrict__ Wk, const float* __restrict__ Wv) {
    int y = blockIdx.y, z = blockIdx.z;
    const float* W; int ldw, n0w, n0c;
    if (y < 32)      { W = Wq; ldw = 4096; n0w = y * 128;        n0c = y * 128; }
    else if (y < 40) { W = Wk; ldw = 1024; n0w = (y - 32) * 128; n0c = 4096 + (y - 32) * 128; }
    else             { W = Wv; ldw = 1024; n0w = (y - 40) * 128; n0c = 5120 + (y - 40) * 128; }
    gemm_tile(x, 4096, W, ldw, g_p[z], NC, blockIdx.x * BM, n0w, n0c, z * 1024, 32);
}

__global__ void out_kernel(const float* __restrict__ Wo) {
    int z = blockIdx.z;
    gemm_tile(g_ctx, 4096, Wo, 4096, g_p[z], 4096,
              blockIdx.x * BM, blockIdx.y * 128, blockIdx.y * 128, z * 1024, 32);
}

// ======================= combines =======================
__global__ void qkv_combine_kernel() {
    int idx = blockIdx.x * 256 + threadIdx.x;
    int row = idx / (NC / 2);
    int p   = idx - row * (NC / 2);
    int col = 2 * p;
    float v0 = 0.f, v1 = 0.f;
#pragma unroll
    for (int h = 0; h < KS; h++) {
        const float* src = g_p[h] + (long)row * NC + col;
        v0 += src[0]; v1 += src[1];
    }
    if (col < 4096) {
        int pp = (col & 127) >> 1;
        float2 cs = g_tab[((row & 15) << 6) + pp];
        // fold 1/sqrt(HD) * log2(e): scores land in base-2 domain
        const float qs = 0.08838834764831845f * 1.4426950408889634f;
        float t = (v0 * cs.x - v1 * cs.y) * qs;
        v1 = (v0 * cs.y + v1 * cs.x) * qs; v0 = t;
        *(float2*)(g_q + (long)row * 4096 + col) = make_float2(v0, v1);
    } else if (col < 5120) {
        int c2 = col - 4096;
        int pp = (c2 & 127) >> 1;
        float2 cs = g_tab[((row & 15) << 6) + pp];
        float t = v0 * cs.x - v1 * cs.y;
        v1 = v0 * cs.y + v1 * cs.x; v0 = t;
        *(float2*)(g_kn + (long)row * 1024 + c2) = make_float2(v0, v1);
    } else {
        *(float2*)(g_vn + (long)row * 1024 + (col - 5120)) = make_float2(v0, v1);
    }
}

__global__ void out_combine_kernel(float* __restrict__ out) {
    int idx = blockIdx.x * 256 + threadIdx.x;
    float4 a = *(const float4*)(g_p[0] + 4 * (long)idx);
    float4 b = *(const float4*)(g_p[1] + 4 * (long)idx);
    float4 c = *(const float4*)(g_p[2] + 4 * (long)idx);
    float4 d = *(const float4*)(g_p[3] + 4 * (long)idx);
    *(float4*)(out + 4 * (long)idx) =
        make_float4(a.x + b.x + c.x + d.x, a.y + b.y + c.y + d.y,
                    a.z + b.z + c.z + d.z, a.w + b.w + c.w + d.w);
}

// ======================= attention (512 thr, TC=64, fp16 softmax+PV) =======================
#define TC   64
#define KSTR 132
#define VSTR 132    // fp32 V staging stride (16B-aligned rows for cp.async)
#define PW   36     // uint32 words per Ph row: fragment reads 4*gr+kq mod 32 -> conflict-free
#define VW   36     // uint32 words per Vh row: same property
#define AOFF_K0  0
#define AOFF_K1  (TC*KSTR)
#define AOFF_V0  (2*TC*KSTR)
#define AOFF_V1  (AOFF_V0 + TC*VSTR)
#define AOFF_PH  (AOFF_V1 + TC*VSTR)     // Ph: 64*PW uint32
#define AOFF_VH  (AOFF_PH + 64*PW)       // Vh: 128*VW uint32
#define AOFF_EX  (AOFF_VH + 128*VW)
#define ATTN_SMEM_BYTES ((AOFF_EX + 512) * 4)

__device__ __forceinline__ void attn_load_kv(
    const float* __restrict__ cache_k, const float* __restrict__ cache_v,
    int b, int kvh, int start, int kvlen, int t0, float* Ks, float* Vs, int tid)
{
#pragma unroll
    for (int i = 0; i < 4; i++) {
        int idx = i * 512 + tid; int r = idx >> 5, c4 = idx & 31;
        int t = t0 + r;
        const float *sk, *sv;
        if (t < start) {
            long o = ((((long)b * MAXS_ + t) * KVH_) + kvh) * HD_ + c4 * 4;
            sk = cache_k + o; sv = cache_v + o;
        } else {
            int tt = min(t, kvlen - 1);
            long o = (((long)(b * S_ + (tt - start))) * KVH_ + kvh) * HD_ + c4 * 4;
            sk = g_kn + o; sv = g_vn + o;
        }
        cpa16(Ks + r * KSTR + c4 * 4, sk);
        cpa16(Vs + r * VSTR + c4 * 4, sv);
    }
    cp_commit();
}

__global__ void __launch_bounds__(512, 1)
attn_kernel(const float* __restrict__ cache_k,
            const float* __restrict__ cache_v,
            const int* __restrict__ sp)
{
    extern __shared__ float sm[];
    float* Ksb[2] = { sm + AOFF_K0, sm + AOFF_K1 };
    float* Vsb[2] = { sm + AOFF_V0, sm + AOFF_V1 };
    unsigned* PhW = (unsigned*)(sm + AOFF_PH);
    unsigned* VhW = (unsigned*)(sm + AOFF_VH);
    float* ex = sm + AOFF_EX;   // [0:256) m partials, [256:512) l partials

    int tid = threadIdx.x, lane = tid & 31, wid = tid >> 5;
    int b = blockIdx.x >> 3, kvh = blockIdx.x & 7;
    int start = sp[0], kvlen = start + S_;
    int wm = wid & 3, wn = wid >> 2;       // 4 m-groups x 4 n-groups
    int gr = lane >> 2, kq = lane & 3;
    int rm = wm * 16;

    // Q fragments (g_q already scaled by 1/sqrt(HD)*log2e)
    unsigned qa[16][4];
    {
        int r0 = rm + gr, r1 = r0 + 8;
        const float* q0 = g_q + (long)(b * S_ + (r0 & 15)) * D_ + (kvh * NREP_ + (r0 >> 4)) * HD_;
        const float* q1 = g_q + (long)(b * S_ + (r1 & 15)) * D_ + (kvh * NREP_ + (r1 >> 4)) * HD_;
#pragma unroll
        for (int kk = 0; kk < 16; kk++) {
            qa[kk][0] = f2tf(q0[kk * 8 + kq]);
            qa[kk][1] = f2tf(q1[kk * 8 + kq]);
            qa[kk][2] = f2tf(q0[kk * 8 + kq + 4]);
            qa[kk][3] = f2tf(q1[kk * 8 + kq + 4]);
        }
    }

    float m0r = -1e30f, m1r = -1e30f, l0r = 0.f, l1r = 0.f;
    float cacc[4][4];
#pragma unroll
    for (int nt = 0; nt < 4; nt++)
#pragma unroll
        for (int i = 0; i < 4; i++) cacc[nt][i] = 0.f;

    int NCH = (kvlen + TC - 1) / TC;
    attn_load_kv(cache_k, cache_v, b, kvh, start, kvlen, 0, Ksb[0], Vsb[0], tid);
    attn_load_kv(cache_k, cache_v, b, kvh, start, kvlen, TC, Ksb[1], Vsb[1], tid);
    cp_wait<1>();
    __syncthreads();

    for (int j = 0; j < NCH; j++) {
        const float* Kb = Ksb[j & 1];
        const float* Vb = Vsb[j & 1];

        // ---- convert V fp32 [t][d] -> fp16 transposed Vh [d][t-pair] ----
        // thread owns one t-pair; lanes sweep consecutive d => conflict-free reads
#pragma unroll
        for (int it = 0; it < 2; it++) {
            int pair = it * 16 + wid;
            const float* v0p = Vb + (2 * pair) * VSTR;
            const float* v1p = Vb + (2 * pair + 1) * VSTR;
#pragma unroll
            for (int dd = 0; dd < 4; dd++) {
                int d = dd * 32 + lane;
                VhW[d * VW + pair] = packh2(v0p[d], v1p[d]);
            }
        }

        // ---- S = Q K^T (tf32) : warp covers cols [wn*16, wn*16+16) ----
        float sacc[2][4];
#pragma unroll
        for (int nt = 0; nt < 2; nt++)
#pragma unroll
            for (int i = 0; i < 4; i++) sacc[nt][i] = 0.f;
#pragma unroll
        for (int kk = 0; kk < 16; kk++) {
#pragma unroll
            for (int nt = 0; nt < 2; nt++) {
                int cb = wn * 16 + nt * 8 + gr;
                unsigned b0 = f2tf(Kb[cb * KSTR + kk * 8 + kq]);
                unsigned b1 = f2tf(Kb[cb * KSTR + kk * 8 + kq + 4]);
                mma8(sacc[nt], qa[kk][0], qa[kk][1], qa[kk][2], qa[kk][3], b0, b1);
            }
        }

        if (j == NCH - 1 && (kvlen & (TC - 1))) {     // never taken for kvlen=4096
#pragma unroll
            for (int nt = 0; nt < 2; nt++) {
                int cb = j * TC + wn * 16 + nt * 8 + 2 * kq;
                if (cb >= kvlen)     { sacc[nt][0] = -1e30f; sacc[nt][2] = -1e30f; }
                if (cb + 1 >= kvlen) { sacc[nt][1] = -1e30f; sacc[nt][3] = -1e30f; }
            }
        }

        // ---- row max across 4 wn warps ----
        float mw0 = fmaxf(fmaxf(sacc[0][0], sacc[0][1]), fmaxf(sacc[1][0], sacc[1][1]));
        float mw1 = fmaxf(fmaxf(sacc[0][2], sacc[0][3]), fmaxf(sacc[1][2], sacc[1][3]));
        mw0 = fmaxf(mw0, __shfl_xor_sync(0xffffffffu, mw0, 1));
        mw0 = fmaxf(mw0, __shfl_xor_sync(0xffffffffu, mw0, 2));
        mw1 = fmaxf(mw1, __shfl_xor_sync(0xffffffffu, mw1, 1));
        mw1 = fmaxf(mw1, __shfl_xor_sync(0xffffffffu, mw1, 2));
        if (kq == 0) { ex[wn * 64 + rm + gr] = mw0; ex[wn * 64 + rm + gr + 8] = mw1; }
        GROUP_BAR(1 + wm);
        float M0 = m0r, M1 = m1r;
#pragma unroll
        for (int w = 0; w < 4; w++) {
            M0 = fmaxf(M0, ex[w * 64 + rm + gr]);
            M1 = fmaxf(M1, ex[w * 64 + rm + gr + 8]);
        }

        // ---- p' = 2^(s - (M-8)) in f16x2 (2 exps per MUFU op) ----
        float Mb0 = M0 - 8.f, Mb1 = M1 - 8.f;
        unsigned pr[2], pr8[2];
#pragma unroll
        for (int nt = 0; nt < 2; nt++) {
            pr[nt]  = h2ex2(packh2(sacc[nt][0] - Mb0, sacc[nt][1] - Mb0));
            pr8[nt] = h2ex2(packh2(sacc[nt][2] - Mb1, sacc[nt][3] - Mb1));
            int w0 = wn * 8 + nt * 4 + kq;      // t-pair index
            PhW[(rm + gr) * PW + w0]     = pr[nt];
            PhW[(rm + gr + 8) * PW + w0] = pr8[nt];
        }
        float2 s0 = h2f2(hadd2u(pr[0], pr[1]));
        float2 s1 = h2f2(hadd2u(pr8[0], pr8[1]));
        float l0l = s0.x + s0.y, l1l = s1.x + s1.y;
        l0l += __shfl_xor_sync(0xffffffffu, l0l, 1);
        l0l += __shfl_xor_sync(0xffffffffu, l0l, 2);
        l1l += __shfl_xor_sync(0xffffffffu, l1l, 1);
        l1l += __shfl_xor_sync(0xffffffffu, l1l, 2);
        if (kq == 0) { ex[256 + wn * 64 + rm + gr] = l0l; ex[256 + wn * 64 + rm + gr + 8] = l1l; }

        __syncthreads();     // Ph, Vh, l-partials visible to all

        float L0 = 0.f, L1 = 0.f;
#pragma unroll
        for (int w = 0; w < 4; w++) {
            L0 += ex[256 + w * 64 + rm + gr];
            L1 += ex[256 + w * 64 + rm + gr + 8];
        }
        if (M0 > m0r || M1 > m1r) {       // rescale only when running max grows
            float sc0 = ex2f(m0r - M0), sc1 = ex2f(m1r - M1);
            l0r *= sc0;  l1r *= sc1;
#pragma unroll
            for (int nt = 0; nt < 4; nt++) {
                cacc[nt][0] *= sc0; cacc[nt][1] *= sc0;
                cacc[nt][2] *= sc1; cacc[nt][3] *= sc1;
            }
            m0r = M0;  m1r = M1;
        }
        l0r += L0;  l1r += L1;

        // ---- O += P V (fp16 m16n8k16): warp covers dims [wn*32, wn*32+32) ----
#pragma unroll
        for (int kb = 0; kb < 4; kb++) {
            unsigned a0 = PhW[(rm + gr) * PW + kb * 8 + kq];
            unsigned a1 = PhW[(rm + gr + 8) * PW + kb * 8 + kq];
            unsigned a2 = PhW[(rm + gr) * PW + kb * 8 + kq + 4];
            unsigned a3 = PhW[(rm + gr + 8) * PW + kb * 8 + kq + 4];
#pragma unroll
            for (int nt = 0; nt < 4; nt++) {
                int dc = wn * 32 + nt * 8;
                unsigned b0 = VhW[(dc + gr) * VW + kb * 8 + kq];
                unsigned b1 = VhW[(dc + gr) * VW + kb * 8 + kq + 4];
                mma16h(cacc[nt], a0, a1, a2, a3, b0, b1);
            }
        }

        cp_wait<0>();
        __syncthreads();     // chunk j+1 resident; PV(j) done; Vh(j) consumed
        if (j + 2 < NCH)
            attn_load_kv(cache_k, cache_v, b, kvh, start, kvlen,
                         (j + 2) * TC, Ksb[j & 1], Vsb[j & 1], tid);
    }

    // ---- epilogue (2^8 bias cancels in the ratio) ----
    float inv0 = 1.f / l0r, inv1 = 1.f / l1r;
    int r0 = rm + gr, r1 = r0 + 8;
    long base0 = (long)(b * S_ + (r0 & 15)) * D_ + (kvh * NREP_ + (r0 >> 4)) * HD_;
    long base1 = (long)(b * S_ + (r1 & 15)) * D_ + (kvh * NREP_ + (r1 >> 4)) * HD_;
#pragma unroll
    for (int nt = 0; nt < 4; nt++) {
        int col = wn * 32 + nt * 8 + 2 * kq;
        *(float2*)(g_ctx + base0 + col) = make_float2(cacc[nt][0] * inv0, cacc[nt][1] * inv0);
        *(float2*)(g_ctx + base1 + col) = make_float2(cacc[nt][2] * inv1, cacc[nt][3] * inv1);
    }
}

// ======================= launch =======================
extern "C" void kernel_launch(void* const* d_in, const int* in_sizes, int n_in,
                              void* d_out, int out_size) {
    const float* x       = (const float*)d_in[0];
    const float* Wq      = (const float*)d_in[1];
    const float* Wk      = (const float*)d_in[2];
    const float* Wv      = (const float*)d_in[3];
    const float* Wo      = (const float*)d_in[4];
    const float* cache_k = (const float*)d_in[5];
    const float* cache_v = (const float*)d_in[6];
    const int*   sp      = (const int*)d_in[7];
    float* out = (float*)d_out;

    cudaFuncSetAttribute(qkv_kernel,  cudaFuncAttributeMaxDynamicSharedMemorySize, GEMM_SMEM_BYTES);
    cudaFuncSetAttribute(out_kernel,  cudaFuncAttributeMaxDynamicSharedMemorySize, GEMM_SMEM_BYTES);
    cudaFuncSetAttribute(attn_kernel, cudaFuncAttributeMaxDynamicSharedMemorySize, ATTN_SMEM_BYTES);

    rope_tab_kernel<<<1, 1024>>>(sp);
    qkv_kernel<<<dim3(2, 48, KS), 256, GEMM_SMEM_BYTES>>>(x, Wq, Wk, Wv);
    qkv_combine_kernel<<<(MROWS * NC / 2) / 256, 256>>>();
    attn_kernel<<<128, 512, ATTN_SMEM_BYTES>>>(cache_k, cache_v, sp);
    out_kernel<<<dim3(2, 32, KS), 256, GEMM_SMEM_BYTES>>>(Wo);
    out_combine_kernel<<<(MROWS * D_ / 4) / 256, 256>>>(out);
}

// round 10
// speedup vs baseline: 1.2964x; 1.0321x over previous
#include <cuda_runtime.h>
#include <cuda_bf16.h>
#include <cstdint>

#define B_    16
#define S_    16
#define D_    4096
#define H_    32
#define KVH_  8
#define HD_   128
#define NREP_ 4
#define MAXS_ 4096
#define MROWS 256
#define KS    4        // K-split factor for projection GEMMs
#define NC    6144     // qkv unified output columns

__device__ float  g_q  [MROWS * D_];
__device__ float  g_kn [MROWS * KVH_ * HD_];
__device__ float  g_vn [MROWS * KVH_ * HD_];
__device__ float  g_ctx[MROWS * D_];
__device__ float  g_p  [KS][MROWS * NC];   // GEMM partials
__device__ float2 g_tab[S_ * 64];          // rope cos/sin [s][pp]

__device__ __forceinline__ unsigned f2tf(float x) {
    unsigned r; asm("cvt.rna.tf32.f32 %0, %1;" : "=r"(r) : "f"(x)); return r;
}
__device__ __forceinline__ void mma8(float* d, unsigned a0, unsigned a1, unsigned a2,
                                     unsigned a3, unsigned b0, unsigned b1) {
    asm volatile(
        "mma.sync.aligned.m16n8k8.row.col.f32.tf32.tf32.f32 "
        "{%0,%1,%2,%3}, {%4,%5,%6,%7}, {%8,%9}, {%0,%1,%2,%3};"
        : "+f"(d[0]), "+f"(d[1]), "+f"(d[2]), "+f"(d[3])
        : "r"(a0), "r"(a1), "r"(a2), "r"(a3), "r"(b0), "r"(b1));
}
__device__ __forceinline__ void mma16h(float* d, unsigned a0, unsigned a1, unsigned a2,
                                       unsigned a3, unsigned b0, unsigned b1) {
    asm volatile(
        "mma.sync.aligned.m16n8k16.row.col.f32.f16.f16.f32 "
        "{%0,%1,%2,%3}, {%4,%5,%6,%7}, {%8,%9}, {%0,%1,%2,%3};"
        : "+f"(d[0]), "+f"(d[1]), "+f"(d[2]), "+f"(d[3])
        : "r"(a0), "r"(a1), "r"(a2), "r"(a3), "r"(b0), "r"(b1));
}
__device__ __forceinline__ float ex2f(float x) {
    float r; asm("ex2.approx.f32 %0, %1;" : "=f"(r) : "f"(x)); return r;
}
__device__ __forceinline__ unsigned packh2(float lo, float hi) {
    unsigned d; asm("cvt.rn.f16x2.f32 %0, %1, %2;" : "=r"(d) : "f"(hi), "f"(lo)); return d;
}
__device__ __forceinline__ void cpa16(float* s, const float* g) {
    unsigned sa = (unsigned)__cvta_generic_to_shared(s);
    asm volatile("cp.async.cg.shared.global [%0], [%1], 16;" :: "r"(sa), "l"(g));
}
__device__ __forceinline__ void cp_commit() { asm volatile("cp.async.commit_group;"); }
template<int N> __device__ __forceinline__ void cp_wait() {
    asm volatile("cp.async.wait_group %0;" :: "n"(N));
}
#define GROUP_BAR(id) asm volatile("bar.sync %0, 128;" :: "r"(id) : "memory")

// ======================= rope table =======================
__global__ void rope_tab_kernel(const int* __restrict__ sp) {
    int idx = threadIdx.x;
    int s = idx >> 6, pp = idx & 63;
    double f = (double)(sp[0] + s) * exp(-9.210340371976184 * ((double)pp / 64.0));
    double cd, sd; sincos(f, &sd, &cd);
    g_tab[idx] = make_float2((float)cd, (float)sd);
}

// ======================= GEMM 128x128, K-split =======================
#define BM 128
#define BK 32
#define AST 36
#define BST 136
#define GEMM_SMEM_BYTES ((2*BM*AST + 2*BK*BST) * 4)

__device__ void gemm_tile(const float* __restrict__ A, int lda,
                          const float* __restrict__ W, int ldw,
                          float* __restrict__ C, int ldc,
                          int m0, int n0w, int n0c, int kbase, int KT)
{
    extern __shared__ float sm[];
    float* As0 = sm;
    float* As1 = sm + BM * AST;
    float* Bs0 = sm + 2 * BM * AST;
    float* Bs1 = sm + 2 * BM * AST + BK * BST;

    int tid = threadIdx.x, lane = tid & 31, wid = tid >> 5;
    int wm = wid >> 2, wn = wid & 3;
    int gr = lane >> 2, kq = lane & 3;

    float acc[4][4][4];
#pragma unroll
    for (int mt = 0; mt < 4; mt++)
#pragma unroll
        for (int nt = 0; nt < 4; nt++)
#pragma unroll
            for (int i = 0; i < 4; i++) acc[mt][nt][i] = 0.f;

    {
#pragma unroll
        for (int i = 0; i < 4; i++) {
            int idx = i * 256 + tid; int r = idx >> 3, c4 = idx & 7;
            cpa16(As0 + r * AST + c4 * 4, A + (long)(m0 + r) * lda + kbase + c4 * 4);
        }
#pragma unroll
        for (int i = 0; i < 4; i++) {
            int idx = i * 256 + tid; int r = idx >> 5, c4 = idx & 31;
            cpa16(Bs0 + r * BST + c4 * 4, W + (long)(kbase + r) * ldw + n0w + c4 * 4);
        }
        cp_commit();
    }

    for (int kt = 0; kt < KT; kt++) {
        float* Ab = (kt & 1) ? As1 : As0;
        float* Bb = (kt & 1) ? Bs1 : Bs0;
        if (kt + 1 < KT) {
            float* An = (kt & 1) ? As0 : As1;
            float* Bn = (kt & 1) ? Bs0 : Bs1;
            int k1 = kbase + (kt + 1) * BK;
#pragma unroll
            for (int i = 0; i < 4; i++) {
                int idx = i * 256 + tid; int r = idx >> 3, c4 = idx & 7;
                cpa16(An + r * AST + c4 * 4, A + (long)(m0 + r) * lda + k1 + c4 * 4);
            }
#pragma unroll
            for (int i = 0; i < 4; i++) {
                int idx = i * 256 + tid; int r = idx >> 5, c4 = idx & 31;
                cpa16(Bn + r * BST + c4 * 4, W + (long)(k1 + r) * ldw + n0w + c4 * 4);
            }
            cp_commit();
            cp_wait<1>();
        } else {
            cp_wait<0>();
        }
        __syncthreads();
#pragma unroll
        for (int kk = 0; kk < 4; kk++) {
            unsigned af[4][4], bf[4][2];
#pragma unroll
            for (int mt = 0; mt < 4; mt++) {
                int rm = wm * 64 + mt * 16;
                const float* p0 = Ab + (rm + gr) * AST + kk * 8 + kq;
                const float* p1 = Ab + (rm + gr + 8) * AST + kk * 8 + kq;
                af[mt][0] = f2tf(p0[0]); af[mt][1] = f2tf(p1[0]);
                af[mt][2] = f2tf(p0[4]); af[mt][3] = f2tf(p1[4]);
            }
#pragma unroll
            for (int nt = 0; nt < 4; nt++) {
                int cb = wn * 32 + nt * 8 + gr;
                bf[nt][0] = f2tf(Bb[(kk * 8 + kq) * BST + cb]);
                bf[nt][1] = f2tf(Bb[(kk * 8 + kq + 4) * BST + cb]);
            }
#pragma unroll
            for (int mt = 0; mt < 4; mt++)
#pragma unroll
                for (int nt = 0; nt < 4; nt++)
                    mma8(acc[mt][nt], af[mt][0], af[mt][1], af[mt][2], af[mt][3],
                         bf[nt][0], bf[nt][1]);
        }
        __syncthreads();
    }

#pragma unroll
    for (int mt = 0; mt < 4; mt++)
#pragma unroll
        for (int nt = 0; nt < 4; nt++) {
            int row = m0 + wm * 64 + mt * 16 + gr;
            int col = n0c + wn * 32 + nt * 8 + 2 * kq;
            *(float2*)(C + (long)row * ldc + col) =
                make_float2(acc[mt][nt][0], acc[mt][nt][1]);
            *(float2*)(C + (long)(row + 8) * ldc + col) =
                make_float2(acc[mt][nt][2], acc[mt][nt][3]);
        }
}

__global__ void qkv_kernel(const float* __restrict__ x, const float* __restrict__ Wq,
                           const float* __restrict__ Wk, const float* __restrict__ Wv) {
    int y = blockIdx.y, z = blockIdx.z;
    const float* W; int ldw, n0w, n0c;
    if (y < 32)      { W = Wq; ldw = 4096; n0w = y * 128;        n0c = y * 128; }
    else if (y < 40) { W = Wk; ldw = 1024; n0w = (y - 32) * 128; n0c = 4096 + (y - 32) * 128; }
    else             { W = Wv; ldw = 1024; n0w = (y - 40) * 128; n0c = 5120 + (y - 40) * 128; }
    gemm_tile(x, 4096, W, ldw, g_p[z], NC, blockIdx.x * BM, n0w, n0c, z * 1024, 32);
}

__global__ void out_kernel(const float* __restrict__ Wo) {
    int z = blockIdx.z;
    gemm_tile(g_ctx, 4096, Wo, 4096, g_p[z], 4096,
              blockIdx.x * BM, blockIdx.y * 128, blockIdx.y * 128, z * 1024, 32);
}

// ======================= combines =======================
__global__ void qkv_combine_kernel() {
    int idx = blockIdx.x * 256 + threadIdx.x;
    int row = idx / (NC / 2);
    int p   = idx - row * (NC / 2);
    int col = 2 * p;
    float v0 = 0.f, v1 = 0.f;
#pragma unroll
    for (int h = 0; h < KS; h++) {
        const float* src = g_p[h] + (long)row * NC + col;
        v0 += src[0]; v1 += src[1];
    }
    if (col < 4096) {
        int pp = (col & 127) >> 1;
        float2 cs = g_tab[((row & 15) << 6) + pp];
        // fold 1/sqrt(HD) * log2(e): scores land in base-2 domain
        const float qs = 0.08838834764831845f * 1.4426950408889634f;
        float t = (v0 * cs.x - v1 * cs.y) * qs;
        v1 = (v0 * cs.y + v1 * cs.x) * qs; v0 = t;
        *(float2*)(g_q + (long)row * 4096 + col) = make_float2(v0, v1);
    } else if (col < 5120) {
        int c2 = col - 4096;
        int pp = (c2 & 127) >> 1;
        float2 cs = g_tab[((row & 15) << 6) + pp];
        float t = v0 * cs.x - v1 * cs.y;
        v1 = v0 * cs.y + v1 * cs.x; v0 = t;
        *(float2*)(g_kn + (long)row * 1024 + c2) = make_float2(v0, v1);
    } else {
        *(float2*)(g_vn + (long)row * 1024 + (col - 5120)) = make_float2(v0, v1);
    }
}

__global__ void out_combine_kernel(float* __restrict__ out) {
    int idx = blockIdx.x * 256 + threadIdx.x;
    float4 a = *(const float4*)(g_p[0] + 4 * (long)idx);
    float4 b = *(const float4*)(g_p[1] + 4 * (long)idx);
    float4 c = *(const float4*)(g_p[2] + 4 * (long)idx);
    float4 d = *(const float4*)(g_p[3] + 4 * (long)idx);
    *(float4*)(out + 4 * (long)idx) =
        make_float4(a.x + b.x + c.x + d.x, a.y + b.y + c.y + d.y,
                    a.z + b.z + c.z + d.z, a.w + b.w + c.w + d.w);
}

// ======================= attention (512 thr, TC=64, all-fp16 mma) =======================
#define TC   64
#define KSTR 132
#define VSTR 132
#define KW   68     // half2 words per Kh row: 64 d-pairs + 4 pad (frag addr 4*gr+kq mod 32)
#define VW   36     // half2 words per Vh row: 32 t-pairs + 4 pad
#define PW   36     // half2 words per Ph row: 32 t-pairs + 4 pad
#define AOFF_K0  0
#define AOFF_K1  (TC*KSTR)
#define AOFF_V0  (2*TC*KSTR)
#define AOFF_V1  (AOFF_V0 + TC*VSTR)
#define AOFF_KH  (AOFF_V1 + TC*VSTR)
#define AOFF_VH  (AOFF_KH + TC*KW)
#define AOFF_PH  (AOFF_VH + 128*VW)
#define AOFF_EX  (AOFF_PH + 64*PW)
#define ATTN_SMEM_BYTES ((AOFF_EX + 512) * 4)

__device__ __forceinline__ void attn_load_kv(
    const float* __restrict__ cache_k, const float* __restrict__ cache_v,
    int b, int kvh, int start, int kvlen, int t0, float* Ks, float* Vs, int tid)
{
#pragma unroll
    for (int i = 0; i < 4; i++) {
        int idx = i * 512 + tid; int r = idx >> 5, c4 = idx & 31;
        int t = t0 + r;
        const float *sk, *sv;
        if (t < start) {
            long o = ((((long)b * MAXS_ + t) * KVH_) + kvh) * HD_ + c4 * 4;
            sk = cache_k + o; sv = cache_v + o;
        } else {
            int tt = min(t, kvlen - 1);
            long o = (((long)(b * S_ + (tt - start))) * KVH_ + kvh) * HD_ + c4 * 4;
            sk = g_kn + o; sv = g_vn + o;
        }
        cpa16(Ks + r * KSTR + c4 * 4, sk);
        cpa16(Vs + r * VSTR + c4 * 4, sv);
    }
    cp_commit();
}

__global__ void __launch_bounds__(512, 1)
attn_kernel(const float* __restrict__ cache_k,
            const float* __restrict__ cache_v,
            const int* __restrict__ sp)
{
    extern __shared__ float sm[];
    float* Ksb[2] = { sm + AOFF_K0, sm + AOFF_K1 };
    float* Vsb[2] = { sm + AOFF_V0, sm + AOFF_V1 };
    unsigned* KhW = (unsigned*)(sm + AOFF_KH);
    unsigned* VhW = (unsigned*)(sm + AOFF_VH);
    unsigned* PhW = (unsigned*)(sm + AOFF_PH);
    float* ex = sm + AOFF_EX;   // [0:256) m partials, [256:512) l partials

    int tid = threadIdx.x, lane = tid & 31, wid = tid >> 5;
    int b = blockIdx.x >> 3, kvh = blockIdx.x & 7;
    int start = sp[0], kvlen = start + S_;
    int wm = wid & 3, wn = wid >> 2;       // 4 m-groups x 4 n-groups
    int gr = lane >> 2, kq = lane & 3;
    int rm = wm * 16;
    int gtid = wm * 32 + lane;             // id within the 4-warp wn-group

    // ---- Q fragments packed fp16 once (g_q pre-scaled by 1/sqrt(HD)*log2e) ----
    unsigned qh[8][4];
    {
        int r0 = rm + gr, r1 = r0 + 8;
        const float* q0 = g_q + (long)(b * S_ + (r0 & 15)) * D_ + (kvh * NREP_ + (r0 >> 4)) * HD_;
        const float* q1 = g_q + (long)(b * S_ + (r1 & 15)) * D_ + (kvh * NREP_ + (r1 >> 4)) * HD_;
#pragma unroll
        for (int kb = 0; kb < 8; kb++) {
            int d0 = kb * 16 + 2 * kq;
            qh[kb][0] = packh2(q0[d0],     q0[d0 + 1]);
            qh[kb][1] = packh2(q1[d0],     q1[d0 + 1]);
            qh[kb][2] = packh2(q0[d0 + 8], q0[d0 + 9]);
            qh[kb][3] = packh2(q1[d0 + 8], q1[d0 + 9]);
        }
    }

    float m0r = -1e30f, m1r = -1e30f, l0r = 0.f, l1r = 0.f;
    float cacc[4][4];
#pragma unroll
    for (int nt = 0; nt < 4; nt++)
#pragma unroll
        for (int i = 0; i < 4; i++) cacc[nt][i] = 0.f;

    int NCH = (kvlen + TC - 1) / TC;
    attn_load_kv(cache_k, cache_v, b, kvh, start, kvlen, 0, Ksb[0], Vsb[0], tid);
    attn_load_kv(cache_k, cache_v, b, kvh, start, kvlen, TC, Ksb[1], Vsb[1], tid);
    cp_wait<1>();
    __syncthreads();

    for (int j = 0; j < NCH; j++) {
        const float* Kb = Ksb[j & 1];
        const float* Vb = Vsb[j & 1];

        // ---- K fp32 -> fp16 half2 [t][d-pair], group wn handles its own 16 tokens ----
        {
            int tok = wn * 16 + (gtid & 15);
            int slot = gtid >> 4;                    // 0..7
            const float* krow = Kb + tok * KSTR;
            unsigned* kdst = KhW + tok * KW;
#pragma unroll
            for (int i = 0; i < 8; i++) {
                int w = slot + 8 * i;
                float2 v = *(const float2*)(krow + 2 * w);
                kdst[w] = packh2(v.x, v.y);
            }
        }
        // ---- V fp32 [t][d] -> fp16 transposed [d][t-pair], group wn handles its 32 dims ----
        {
            int d = wn * 32 + (gtid & 31);
            int psub = gtid >> 5;                    // 0..3
#pragma unroll
            for (int i = 0; i < 8; i++) {
                int p = psub * 8 + i;
                float lo = Vb[(2 * p) * VSTR + d];
                float hi = Vb[(2 * p + 1) * VSTR + d];
                VhW[d * VW + p] = packh2(lo, hi);
            }
        }
        GROUP_BAR(5 + wn);    // group's Kh tokens + Vh dims complete

        // ---- S = Q K^T (fp16 m16n8k16): warp covers cols [wn*16, wn*16+16) ----
        float sacc[2][4];
#pragma unroll
        for (int nt = 0; nt < 2; nt++)
#pragma unroll
            for (int i = 0; i < 4; i++) sacc[nt][i] = 0.f;
#pragma unroll
        for (int kb = 0; kb < 8; kb++) {
#pragma unroll
            for (int nt = 0; nt < 2; nt++) {
                int cb = wn * 16 + nt * 8;
                unsigned b0 = KhW[(cb + gr) * KW + kb * 8 + kq];
                unsigned b1 = KhW[(cb + gr) * KW + kb * 8 + kq + 4];
                mma16h(sacc[nt], qh[kb][0], qh[kb][1], qh[kb][2], qh[kb][3], b0, b1);
            }
        }

        if (j == NCH - 1 && (kvlen & (TC - 1))) {     // never taken for kvlen=4096
#pragma unroll
            for (int nt = 0; nt < 2; nt++) {
                int cb = j * TC + wn * 16 + nt * 8 + 2 * kq;
                if (cb >= kvlen)     { sacc[nt][0] = -1e30f; sacc[nt][2] = -1e30f; }
                if (cb + 1 >= kvlen) { sacc[nt][1] = -1e30f; sacc[nt][3] = -1e30f; }
            }
        }

        // ---- row max across 4 wn warps ----
        float mw0 = fmaxf(fmaxf(sacc[0][0], sacc[0][1]), fmaxf(sacc[1][0], sacc[1][1]));
        float mw1 = fmaxf(fmaxf(sacc[0][2], sacc[0][3]), fmaxf(sacc[1][2], sacc[1][3]));
        mw0 = fmaxf(mw0, __shfl_xor_sync(0xffffffffu, mw0, 1));
        mw0 = fmaxf(mw0, __shfl_xor_sync(0xffffffffu, mw0, 2));
        mw1 = fmaxf(mw1, __shfl_xor_sync(0xffffffffu, mw1, 1));
        mw1 = fmaxf(mw1, __shfl_xor_sync(0xffffffffu, mw1, 2));
        if (kq == 0) { ex[wn * 64 + rm + gr] = mw0; ex[wn * 64 + rm + gr + 8] = mw1; }
        GROUP_BAR(1 + wm);
        float M0 = m0r, M1 = m1r;
#pragma unroll
        for (int w = 0; w < 4; w++) {
            M0 = fmaxf(M0, ex[w * 64 + rm + gr]);
            M1 = fmaxf(M1, ex[w * 64 + rm + gr + 8]);
        }

        // ---- p' = 2^(s-(M-8)): fp32 arg + fp32 ex2, packed to fp16 for PV ----
        float Mb0 = M0 - 8.f, Mb1 = M1 - 8.f;
        float e00 = ex2f(sacc[0][0] - Mb0), e01 = ex2f(sacc[0][1] - Mb0);
        float e10 = ex2f(sacc[1][0] - Mb0), e11 = ex2f(sacc[1][1] - Mb0);
        float f00 = ex2f(sacc[0][2] - Mb1), f01 = ex2f(sacc[0][3] - Mb1);
        float f10 = ex2f(sacc[1][2] - Mb1), f11 = ex2f(sacc[1][3] - Mb1);
        {
            int w0 = wn * 8 + kq;
            PhW[(rm + gr) * PW + w0]         = packh2(e00, e01);
            PhW[(rm + gr) * PW + w0 + 4]     = packh2(e10, e11);
            PhW[(rm + gr + 8) * PW + w0]     = packh2(f00, f01);
            PhW[(rm + gr + 8) * PW + w0 + 4] = packh2(f10, f11);
        }
        float l0l = (e00 + e01) + (e10 + e11);
        float l1l = (f00 + f01) + (f10 + f11);
        l0l += __shfl_xor_sync(0xffffffffu, l0l, 1);
        l0l += __shfl_xor_sync(0xffffffffu, l0l, 2);
        l1l += __shfl_xor_sync(0xffffffffu, l1l, 1);
        l1l += __shfl_xor_sync(0xffffffffu, l1l, 2);
        if (kq == 0) { ex[256 + wn * 64 + rm + gr] = l0l; ex[256 + wn * 64 + rm + gr + 8] = l1l; }
        GROUP_BAR(1 + wm);    // P rows + l partials of this wm group visible

        float L0 = 0.f, L1 = 0.f;
#pragma unroll
        for (int w = 0; w < 4; w++) {
            L0 += ex[256 + w * 64 + rm + gr];
            L1 += ex[256 + w * 64 + rm + gr + 8];
        }
        if (M0 > m0r || M1 > m1r) {
            float sc0 = ex2f(m0r - M0), sc1 = ex2f(m1r - M1);
            l0r *= sc0;  l1r *= sc1;
#pragma unroll
            for (int nt = 0; nt < 4; nt++) {
                cacc[nt][0] *= sc0; cacc[nt][1] *= sc0;
                cacc[nt][2] *= sc1; cacc[nt][3] *= sc1;
            }
            m0r = M0;  m1r = M1;
        }
        l0r += L0;  l1r += L1;

        // ---- O += P V (fp16 m16n8k16): warp covers dims [wn*32, wn*32+32) ----
#pragma unroll
        for (int kb = 0; kb < 4; kb++) {
            unsigned a0 = PhW[(rm + gr) * PW + kb * 8 + kq];
            unsigned a1 = PhW[(rm + gr + 8) * PW + kb * 8 + kq];
            unsigned a2 = PhW[(rm + gr) * PW + kb * 8 + kq + 4];
            unsigned a3 = PhW[(rm + gr + 8) * PW + kb * 8 + kq + 4];
#pragma unroll
            for (int nt = 0; nt < 4; nt++) {
                int dc = wn * 32 + nt * 8;
                unsigned b0 = VhW[(dc + gr) * VW + kb * 8 + kq];
                unsigned b1 = VhW[(dc + gr) * VW + kb * 8 + kq + 4];
                mma16h(cacc[nt], a0, a1, a2, a3, b0, b1);
            }
        }

        cp_wait<0>();
        __syncthreads();     // chunk j+1 resident; Kh/Vh/Ph(j) consumed everywhere
        if (j + 2 < NCH)
            attn_load_kv(cache_k, cache_v, b, kvh, start, kvlen,
                         (j + 2) * TC, Ksb[j & 1], Vsb[j & 1], tid);
    }

    // ---- epilogue (2^8 bias cancels in the ratio) ----
    float inv0 = 1.f / l0r, inv1 = 1.f / l1r;
    int r0 = rm + gr, r1 = r0 + 8;
    long base0 = (long)(b * S_ + (r0 & 15)) * D_ + (kvh * NREP_ + (r0 >> 4)) * HD_;
    long base1 = (long)(b * S_ + (r1 & 15)) * D_ + (kvh * NREP_ + (r1 >> 4)) * HD_;
#pragma unroll
    for (int nt = 0; nt < 4; nt++) {
        int col = wn * 32 + nt * 8 + 2 * kq;
        *(float2*)(g_ctx + base0 + col) = make_float2(cacc[nt][0] * inv0, cacc[nt][1] * inv0);
        *(float2*)(g_ctx + base1 + col) = make_float2(cacc[nt][2] * inv1, cacc[nt][3] * inv1);
    }
}

// ======================= launch =======================
extern "C" void kernel_launch(void* const* d_in, const int* in_sizes, int n_in,
                              void* d_out, int out_size) {
    const float* x       = (const float*)d_in[0];
    const float* Wq      = (const float*)d_in[1];
    const float* Wk      = (const float*)d_in[2];
    const float* Wv      = (const float*)d_in[3];
    const float* Wo      = (const float*)d_in[4];
    const float* cache_k = (const float*)d_in[5];
    const float* cache_v = (const float*)d_in[6];
    const int*   sp      = (const int*)d_in[7];
    float* out = (float*)d_out;

    cudaFuncSetAttribute(qkv_kernel,  cudaFuncAttributeMaxDynamicSharedMemorySize, GEMM_SMEM_BYTES);
    cudaFuncSetAttribute(out_kernel,  cudaFuncAttributeMaxDynamicSharedMemorySize, GEMM_SMEM_BYTES);
    cudaFuncSetAttribute(attn_kernel, cudaFuncAttributeMaxDynamicSharedMemorySize, ATTN_SMEM_BYTES);

    rope_tab_kernel<<<1, 1024>>>(sp);
    qkv_kernel<<<dim3(2, 48, KS), 256, GEMM_SMEM_BYTES>>>(x, Wq, Wk, Wv);
    qkv_combine_kernel<<<(MROWS * NC / 2) / 256, 256>>>();
    attn_kernel<<<128, 512, ATTN_SMEM_BYTES>>>(cache_k, cache_v, sp);
    out_kernel<<<dim3(2, 32, KS), 256, GEMM_SMEM_BYTES>>>(Wo);
    out_combine_kernel<<<(MROWS * D_ / 4) / 256, 256>>>(out);
}